// round 2
// baseline (speedup 1.0000x reference)
#include <cuda_runtime.h>
#include <cstdint>
#include <cstddef>

#define DI __device__ __forceinline__

static const int D_DIM = 512;   // embedding dim (fixed for this problem)
#define MAXN 32768
#define MAXK 1024

// Force precise libdevice log regardless of -use_fast_math (XLA uses __nv_logf;
// argmax selection requires bitwise-identical gumbel values).
extern "C" __device__ float __nv_logf(float);

// Scratch (device globals: no allocation allowed in kernel_launch)
__device__ float g_x[(size_t)MAXN * D_DIM];     // 64 MB: 0.5*norm(state)+0.5*norm(adv)
__device__ float g_cn[(size_t)MAXK * D_DIM];    //  2 MB: normalized codebook
__device__ float g_sim[(size_t)MAXN * MAXK];    // 128 MB: similarity logits

// ---------------------------------------------------------------------------
// Threefry-2x32 (exact JAX implementation)
// ---------------------------------------------------------------------------
__host__ __device__ inline uint32_t rotl32(uint32_t x, int r) {
    return (x << r) | (x >> (32 - r));
}

__host__ __device__ inline void threefry2x32(uint32_t k0, uint32_t k1,
                                             uint32_t& x0, uint32_t& x1) {
    uint32_t k2 = k0 ^ k1 ^ 0x1BD11BDAu;
    x0 += k0; x1 += k1;
#define TFR(r) { x0 += x1; x1 = rotl32(x1, r); x1 ^= x0; }
    TFR(13) TFR(15) TFR(26) TFR(6)
    x0 += k1; x1 += k2 + 1u;
    TFR(17) TFR(29) TFR(16) TFR(24)
    x0 += k2; x1 += k0 + 2u;
    TFR(13) TFR(15) TFR(26) TFR(6)
    x0 += k0; x1 += k1 + 3u;
    TFR(17) TFR(29) TFR(16) TFR(24)
    x0 += k1; x1 += k2 + 4u;
    TFR(13) TFR(15) TFR(26) TFR(6)
    x0 += k2; x1 += k0 + 5u;
#undef TFR
}

// JAX partitionable mode, 32-bit random bits for element index i (< 2^32):
//   (o0, o1) = threefry(key, x0 = hi64(i) = 0, x1 = lo64(i) = i);  bits = o0 ^ o1
DI uint32_t tf_bits_partitionable(uint32_t k0, uint32_t k1, uint32_t i) {
    uint32_t x0 = 0u, x1 = i;
    threefry2x32(k0, k1, x0, x1);
    return x0 ^ x1;
}

// JAX: uniform(minval=tiny,maxval=1) -> gumbel = -log(-log(u)); bitwise libdevice log
DI float gumbel_from_bits(uint32_t bits) {
    float u = __uint_as_float((bits >> 9) | 0x3f800000u) - 1.0f;
    const float TINY = 1.17549435e-38f;
    float r = fmaxf(TINY, u + TINY);
    return -__nv_logf(-__nv_logf(r));
}

// ---------------------------------------------------------------------------
// Packed fp32x2 FMA helpers (sm_100+ PTX; ptxas never auto-emits FFMA2)
// ---------------------------------------------------------------------------
typedef unsigned long long u64;
DI u64 pk2(float lo, float hi) {
    u64 r; asm("mov.b64 %0, {%1,%2};" : "=l"(r) : "f"(lo), "f"(hi)); return r;
}
DI void upk2(u64 p, float& lo, float& hi) {
    asm("mov.b64 {%0,%1}, %2;" : "=f"(lo), "=f"(hi) : "l"(p));
}
DI u64 fma2(u64 a, u64 b, u64 c) {
    u64 d; asm("fma.rn.f32x2 %0, %1, %2, %3;" : "=l"(d) : "l"(a), "l"(b), "l"(c));
    return d;
}

// ---------------------------------------------------------------------------
// Kernel 1: normalize codebook rows -> g_cn
// ---------------------------------------------------------------------------
__global__ void norm_cb_kernel(const float* __restrict__ cb) {
    int r = blockIdx.x, t = threadIdx.x;   // 128 threads, D=512 -> 4/thread
    const float* row = cb + (size_t)r * D_DIM;
    float v[4]; float ss = 0.f;
#pragma unroll
    for (int i = 0; i < 4; i++) { v[i] = row[t + i * 128]; ss += v[i] * v[i]; }
    __shared__ float s4[4];
    for (int o = 16; o; o >>= 1) ss += __shfl_down_sync(0xffffffffu, ss, o);
    if ((t & 31) == 0) s4[t >> 5] = ss;
    __syncthreads();
    float nrm = fmaxf(sqrtf(s4[0] + s4[1] + s4[2] + s4[3]), 1e-8f);
    float* orow = g_cn + (size_t)r * D_DIM;
#pragma unroll
    for (int i = 0; i < 4; i++) orow[t + i * 128] = v[i] / nrm;
}

// ---------------------------------------------------------------------------
// Kernel 2: x = 0.5*state/||state|| + 0.5*adv/||adv|| -> g_x
// ---------------------------------------------------------------------------
__global__ void combine_kernel(const float* __restrict__ st,
                               const float* __restrict__ ad) {
    int r = blockIdx.x, t = threadIdx.x;
    const float* s = st + (size_t)r * D_DIM;
    const float* a = ad + (size_t)r * D_DIM;
    float sv[4], av[4]; float ssum = 0.f, asum = 0.f;
#pragma unroll
    for (int i = 0; i < 4; i++) {
        sv[i] = s[t + i * 128]; ssum += sv[i] * sv[i];
        av[i] = a[t + i * 128]; asum += av[i] * av[i];
    }
    __shared__ float s4[4], a4[4];
    for (int o = 16; o; o >>= 1) {
        ssum += __shfl_down_sync(0xffffffffu, ssum, o);
        asum += __shfl_down_sync(0xffffffffu, asum, o);
    }
    if ((t & 31) == 0) { s4[t >> 5] = ssum; a4[t >> 5] = asum; }
    __syncthreads();
    float ns = fmaxf(sqrtf(s4[0] + s4[1] + s4[2] + s4[3]), 1e-8f);
    float na = fmaxf(sqrtf(a4[0] + a4[1] + a4[2] + a4[3]), 1e-8f);
    float* x = g_x + (size_t)r * D_DIM;
#pragma unroll
    for (int i = 0; i < 4; i++)
        x[t + i * 128] = 0.5f * (sv[i] / ns) + 0.5f * (av[i] / na);
}

// ---------------------------------------------------------------------------
// Kernel 3: fp32 NT-GEMM via packed f32x2 FMA
//   g_sim[m,k] = sum_d g_x[m,d] * g_cn[k,d]
//   128x128 tile, BK=16, 256 threads, 8x8 micro-tile (as 8x4 f32x2 pairs)
// ---------------------------------------------------------------------------
__global__ __launch_bounds__(256, 2) void gemm_kernel(int M, int NC) {
    __shared__ float As[16][128 + 4];
    __shared__ float Bs[16][128 + 4];
    const int t = threadIdx.x;
    const int tx = t & 15, ty = t >> 4;
    const int bm = blockIdx.y * 128, bn = blockIdx.x * 128;

    u64 acc[8][4];
#pragma unroll
    for (int i = 0; i < 8; i++)
#pragma unroll
        for (int j = 0; j < 4; j++) acc[i][j] = 0ull;

    for (int d0 = 0; d0 < D_DIM; d0 += 16) {
#pragma unroll
        for (int i = 0; i < 2; i++) {
            int idx = t + i * 256;          // 0..511
            int row = idx >> 2;             // 0..127
            int c4  = (idx & 3) << 2;       // 0,4,8,12
            float4 va = *(const float4*)(g_x + (size_t)(bm + row) * D_DIM + d0 + c4);
            As[c4 + 0][row] = va.x; As[c4 + 1][row] = va.y;
            As[c4 + 2][row] = va.z; As[c4 + 3][row] = va.w;
            float4 vb = *(const float4*)(g_cn + (size_t)(bn + row) * D_DIM + d0 + c4);
            Bs[c4 + 0][row] = vb.x; Bs[c4 + 1][row] = vb.y;
            Bs[c4 + 2][row] = vb.z; Bs[c4 + 3][row] = vb.w;
        }
        __syncthreads();
#pragma unroll
        for (int kk = 0; kk < 16; kk++) {
            float a[8], b[8];
            *(float4*)(a)     = *(const float4*)(&As[kk][ty * 8]);
            *(float4*)(a + 4) = *(const float4*)(&As[kk][ty * 8 + 4]);
            *(float4*)(b)     = *(const float4*)(&Bs[kk][tx * 8]);
            *(float4*)(b + 4) = *(const float4*)(&Bs[kk][tx * 8 + 4]);
            u64 b2[4];
#pragma unroll
            for (int j = 0; j < 4; j++) b2[j] = pk2(b[2 * j], b[2 * j + 1]);
#pragma unroll
            for (int i = 0; i < 8; i++) {
                u64 a2 = pk2(a[i], a[i]);
#pragma unroll
                for (int j = 0; j < 4; j++) acc[i][j] = fma2(a2, b2[j], acc[i][j]);
            }
        }
        __syncthreads();
    }
#pragma unroll
    for (int i = 0; i < 8; i++) {
        float o[8];
#pragma unroll
        for (int j = 0; j < 4; j++) upk2(acc[i][j], o[2 * j], o[2 * j + 1]);
        float* crow = g_sim + (size_t)(bm + ty * 8 + i) * NC + bn + tx * 8;
        *(float4*)(crow)     = make_float4(o[0], o[1], o[2], o[3]);
        *(float4*)(crow + 4) = make_float4(o[4], o[5], o[6], o[7]);
    }
}

// ---------------------------------------------------------------------------
// Kernel 4: gumbel noise (partitionable threefry) + argmax(hard) + softmax(soft)
//   + codebook gather. One block per row n; element (n,k) uses counter n*K+k.
// ---------------------------------------------------------------------------
__global__ void finalize_kernel(const float* __restrict__ cb,
                                float* __restrict__ zq,
                                float* __restrict__ ws,
                                float* __restrict__ idxo,
                                uint32_t g1a, uint32_t g1b,
                                uint32_t g2a, uint32_t g2b,
                                int N, int K) {
    const int T = 256, V = 4;  // K = 1024 = T*V
    int t = threadIdx.x;
    int n = blockIdx.x;

    float l1[V], l2[V];
#pragma unroll
    for (int v = 0; v < V; v++) {
        int k = t + v * T;
        uint32_t i = (uint32_t)n * (uint32_t)K + (uint32_t)k;
        float s = g_sim[(size_t)n * K + k];
        l1[v] = s + gumbel_from_bits(tf_bits_partitionable(g1a, g1b, i));
        l2[v] = s + gumbel_from_bits(tf_bits_partitionable(g2a, g2b, i));
    }

    __shared__ float sv8[8];
    __shared__ int   si8[8];

    // ---- argmax(sim + g1)  (first-occurrence on exact ties)
    float bv = l1[0]; int bi = t;
#pragma unroll
    for (int v = 1; v < V; v++) {
        float x = l1[v];
        if (x > bv) { bv = x; bi = t + v * T; }
    }
    for (int o = 16; o; o >>= 1) {
        float ov = __shfl_down_sync(0xffffffffu, bv, o);
        int   oi = __shfl_down_sync(0xffffffffu, bi, o);
        if (ov > bv || (ov == bv && oi < bi)) { bv = ov; bi = oi; }
    }
    if ((t & 31) == 0) { sv8[t >> 5] = bv; si8[t >> 5] = bi; }
    __syncthreads();
    int best;
    {
        float v0 = sv8[0]; int i0 = si8[0];
#pragma unroll
        for (int w = 1; w < 8; w++)
            if (sv8[w] > v0 || (sv8[w] == v0 && si8[w] < i0)) { v0 = sv8[w]; i0 = si8[w]; }
        best = i0;
    }
    __syncthreads();

    // ---- softmax(sim + g2)
    float m = l2[0];
#pragma unroll
    for (int v = 1; v < V; v++) m = fmaxf(m, l2[v]);
    for (int o = 16; o; o >>= 1) m = fmaxf(m, __shfl_down_sync(0xffffffffu, m, o));
    if ((t & 31) == 0) sv8[t >> 5] = m;
    __syncthreads();
    m = sv8[0];
#pragma unroll
    for (int w = 1; w < 8; w++) m = fmaxf(m, sv8[w]);
    __syncthreads();

    float e[V]; float s = 0.f;
#pragma unroll
    for (int v = 0; v < V; v++) { e[v] = expf(l2[v] - m); s += e[v]; }
    for (int o = 16; o; o >>= 1) s += __shfl_down_sync(0xffffffffu, s, o);
    if ((t & 31) == 0) sv8[t >> 5] = s;
    __syncthreads();
    float tot = sv8[0] + sv8[1] + sv8[2] + sv8[3] + sv8[4] + sv8[5] + sv8[6] + sv8[7];

    float* wrow = ws + (size_t)n * K;
#pragma unroll
    for (int v = 0; v < V; v++) wrow[t + v * T] = e[v] / tot;

    // ---- z_q = codebook[best], indices
    const float* crow = cb + (size_t)best * D_DIM;
    float* zrow = zq + (size_t)n * D_DIM;
    for (int d = t; d < D_DIM; d += T) zrow[d] = crow[d];
    if (t == 0) idxo[n] = (float)best;
}

// ---------------------------------------------------------------------------
extern "C" void kernel_launch(void* const* d_in, const int* in_sizes, int n_in,
                              void* d_out, int out_size) {
    const float* st = (const float*)d_in[0];
    const float* ad = (const float*)d_in[1];
    const float* cb = (const float*)d_in[2];
    int N = in_sizes[0] / D_DIM;     // 32768
    int K = in_sizes[2] / D_DIM;     // 1024

    float* out  = (float*)d_out;
    float* zq   = out;                              // [N, D]
    float* ws   = out + (size_t)N * D_DIM;          // [N, K]
    float* idxo = ws + (size_t)N * K;               // [N, 1]

    // jax.random.key(42) -> (0,42). Partitionable (fold-like) split:
    //   child i = both output words of threefry((0,42), x0=0, x1=i)
    uint32_t g1a = 0u, g1b = 0u;
    threefry2x32(0u, 42u, g1a, g1b);    // counter 0 -> gk1 = (x0_out, x1_out)
    uint32_t g2a = 0u, g2b = 1u;
    threefry2x32(0u, 42u, g2a, g2b);    // counter 1 -> gk2

    norm_cb_kernel<<<K, 128>>>(cb);
    combine_kernel<<<N, 128>>>(st, ad);
    dim3 gg(K / 128, N / 128);
    gemm_kernel<<<gg, 256>>>(N, K);
    finalize_kernel<<<N, 256>>>(cb, zq, ws, idxo, g1a, g1b, g2a, g2b, N, K);
}